// round 15
// baseline (speedup 1.0000x reference)
#include <cuda_runtime.h>
#include <cuda_fp16.h>
#include <math.h>
#include <cstdint>

// Problem constants
#define BATCH 4
#define CIN   3
#define HW    224
#define PATCH 16
#define DIM   256
#define HEADS 8
#define HD    32
#define HP    14
#define NTOK  196
#define DP    8192
#define PIX   50176
#define AK    208          // padded k-stride for g_attn rows (halves), zero-filled

typedef unsigned long long u64t;

// ---------------- scratch (device globals) ----------------------------------
__device__ __align__(16) float  g_q[BATCH * HEADS * NTOK * HD];
__device__ __align__(16) float  g_k[BATCH * HEADS * NTOK * HD];
__device__ __align__(16) __half g_attn[(size_t)BATCH * HEADS * NTOK * AK];   // [n][k]
__device__ __align__(16) __half g_vu[(size_t)BATCH * HEADS * NTOK * DP];     // [m][d']
__device__ __align__(16) __half g_pre[(size_t)BATCH * DIM * PIX];            // [c][pix]
__device__ __align__(16) __half g_pw[DIM * DIM];                             // [co][c]

__device__ __forceinline__ uint32_t smem_u32(const void* p) {
    uint32_t a;
    asm("{ .reg .u64 t; cvta.to.shared.u64 t, %1; cvt.u32.u64 %0, t; }" : "=r"(a) : "l"(p));
    return a;
}
__device__ __forceinline__ u64t pack2(float lo, float hi) {
    u64t r; asm("mov.b64 %0, {%1,%2};" : "=l"(r) : "f"(lo), "f"(hi)); return r;
}
__device__ __forceinline__ void unpack2(u64t v, float& lo, float& hi) {
    asm("mov.b64 {%0,%1}, %2;" : "=f"(lo), "=f"(hi) : "l"(v));
}
__device__ __forceinline__ u64t fma2(u64t a, u64t b, u64t c) {
    u64t d; asm("fma.rn.f32x2 %0, %1, %2, %3;" : "=l"(d) : "l"(a), "l"(b), "l"(c));
    return d;
}
__device__ __forceinline__ void mma_f16(float d[4],
        uint32_t a0, uint32_t a1, uint32_t a2, uint32_t a3,
        uint32_t b0, uint32_t b1) {
    asm volatile(
        "mma.sync.aligned.m16n8k16.row.col.f32.f16.f16.f32 "
        "{%0,%1,%2,%3}, {%4,%5,%6,%7}, {%8,%9}, {%0,%1,%2,%3};"
        : "+f"(d[0]), "+f"(d[1]), "+f"(d[2]), "+f"(d[3])
        : "r"(a0), "r"(a1), "r"(a2), "r"(a3), "r"(b0), "r"(b1));
}
__device__ __forceinline__ void ldsm_x4(uint32_t& r0, uint32_t& r1,
                                        uint32_t& r2, uint32_t& r3, uint32_t addr) {
    asm volatile("ldmatrix.sync.aligned.m8n8.x4.shared.b16 {%0,%1,%2,%3}, [%4];"
                 : "=r"(r0), "=r"(r1), "=r"(r2), "=r"(r3) : "r"(addr));
}
__device__ __forceinline__ void ldsm_x4_t(uint32_t& r0, uint32_t& r1,
                                          uint32_t& r2, uint32_t& r3, uint32_t addr) {
    asm volatile("ldmatrix.sync.aligned.m8n8.x4.trans.shared.b16 {%0,%1,%2,%3}, [%4];"
                 : "=r"(r0), "=r"(r1), "=r"(r2), "=r"(r3) : "r"(addr));
}
__device__ __forceinline__ void cp16(uint32_t dst, const void* src, bool pred) {
    asm volatile("cp.async.cg.shared.global [%0], [%1], 16, %2;"
                 :: "r"(dst), "l"(src), "r"(pred ? 16 : 0) : "memory");
}
#define CP_COMMIT() asm volatile("cp.async.commit_group;" ::: "memory")
#define CP_WAIT2()  asm volatile("cp.async.wait_group 2;" ::: "memory")

// ---------------- 0) round proj_w to fp16 ------------------------------------
__global__ void cvt_pw_kernel(const float* __restrict__ pw) {
    int i = blockIdx.x * 256 + threadIdx.x;
    g_pw[i] = __float2half(pw[i]);
}

// ---------------- 1) fused patch embed + qk ----------------------------------
__global__ __launch_bounds__(256) void patchqk16(const float* __restrict__ x,
                                                 const float* __restrict__ w,
                                                 const float* __restrict__ bias,
                                                 const float* __restrict__ qkw) {
    const int bn0 = blockIdx.x * 8;
    __shared__ __align__(16) float sp[8][768];
    __shared__ __align__(16) float sx[8][256];
    for (int idx = threadIdx.x; idx < 8 * 768; idx += 256) {
        int i = idx / 768, j = idx - (idx / 768) * 768;
        int bn = bn0 + i;
        int b = bn / NTOK, n = bn % NTOK;
        int hp = n / HP, wp = n % HP;
        int ci = j >> 8, r = (j >> 4) & 15, cc = j & 15;
        sp[i][j] = x[(((size_t)b * CIN + ci) * HW + hp * PATCH + r) * HW + wp * PATCH + cc];
    }
    __syncthreads();
    const int co = threadIdx.x;
    {
        const float4* wr = (const float4*)(w + (size_t)co * 768);
        float acc[8] = {};
#pragma unroll 2
        for (int j4 = 0; j4 < 192; j4++) {
            float4 w4 = wr[j4];
#pragma unroll
            for (int i = 0; i < 8; i++) {
                float4 s4 = *(const float4*)&sp[i][j4 * 4];
                acc[i] = fmaf(s4.x, w4.x, fmaf(s4.y, w4.y, fmaf(s4.z, w4.z, fmaf(s4.w, w4.w, acc[i]))));
            }
        }
        float bco = bias[co];
#pragma unroll
        for (int i = 0; i < 8; i++) sx[i][co] = acc[i] + bco;
    }
    __syncthreads();
    {
        const float4* w0 = (const float4*)(qkw + (size_t)co * DIM);
        const float4* w1 = (const float4*)(qkw + (size_t)(DIM + co) * DIM);
        float acc0[8] = {}, acc1[8] = {};
#pragma unroll 2
        for (int j4 = 0; j4 < 64; j4++) {
            float4 a = w0[j4];
            float4 bq = w1[j4];
#pragma unroll
            for (int i = 0; i < 8; i++) {
                float4 s4 = *(const float4*)&sx[i][j4 * 4];
                acc0[i] = fmaf(s4.x, a.x,  fmaf(s4.y, a.y,  fmaf(s4.z, a.z,  fmaf(s4.w, a.w,  acc0[i]))));
                acc1[i] = fmaf(s4.x, bq.x, fmaf(s4.y, bq.y, fmaf(s4.z, bq.z, fmaf(s4.w, bq.w, acc1[i]))));
            }
        }
        const int h = co >> 5, d = co & 31;
#pragma unroll
        for (int i = 0; i < 8; i++) {
            int bn = bn0 + i;
            int b = bn / NTOK, n = bn % NTOK;
            size_t off = (((size_t)b * HEADS + h) * NTOK + n) * HD + d;
            g_q[off] = acc0[i];
            g_k[off] = acc1[i];
        }
    }
}

// ---------------- 2) scores + softmax -> attn (fp16, pad zeroed) -------------
__global__ __launch_bounds__(256) void softmax_v2() {
    const int bh = blockIdx.x;
    __shared__ float sk[NTOK][33];
    const float* kb = g_k + (size_t)bh * NTOK * HD;
    for (int i = threadIdx.x; i < NTOK * HD; i += 256)
        sk[i >> 5][i & 31] = kb[i];
    __syncthreads();
    const int wid = threadIdx.x >> 5, lane = threadIdx.x & 31;
    for (int n = wid; n < NTOK; n += 8) {
        float qd = g_q[((size_t)bh * NTOK + n) * HD + lane];
        float acc[7] = {};
#pragma unroll
        for (int d = 0; d < HD; d++) {
            float qv = __shfl_sync(0xffffffffu, qd, d);
#pragma unroll
            for (int j = 0; j < 7; j++) {
                int m = j * 32 + lane;
                int mc = m < NTOK ? m : NTOK - 1;
                acc[j] = fmaf(qv, sk[mc][d], acc[j]);
            }
        }
        float sc[7], mx = -INFINITY;
#pragma unroll
        for (int j = 0; j < 7; j++) {
            int m = j * 32 + lane;
            sc[j] = (m < NTOK) ? acc[j] * 0.17677669529663687f : -INFINITY;
            mx = fmaxf(mx, sc[j]);
        }
#pragma unroll
        for (int off = 16; off > 0; off >>= 1)
            mx = fmaxf(mx, __shfl_xor_sync(0xffffffffu, mx, off));
        float sum = 0.f;
#pragma unroll
        for (int j = 0; j < 7; j++) {
            sc[j] = expf(sc[j] - mx);
            sum += sc[j];
        }
#pragma unroll
        for (int off = 16; off > 0; off >>= 1)
            sum += __shfl_xor_sync(0xffffffffu, sum, off);
        float inv = 1.f / sum;
        __half* arow = g_attn + ((size_t)bh * NTOK + n) * AK;
#pragma unroll
        for (int j = 0; j < 7; j++) {
            int m = j * 32 + lane;
            if (m < NTOK)      arow[m] = __float2half(sc[j] * inv);
            else if (m < AK)   arow[m] = __float2half(0.f);
        }
    }
}

// ---------------- 3) conv3x3 (V) + unfold -> vu : packed f32x2 FFMA2 ---------
__global__ __launch_bounds__(256) void convv_unfold_kernel(
        const float* __restrict__ x,
        const float* __restrict__ vw,
        const float* __restrict__ vb) {
    const int y = blockIdx.x;
    const int b = blockIdx.y;
    __shared__ __align__(16) float srow[CIN][3][226];
    __shared__ __align__(16) u64t sw2[128][28];   // (w[2p][j], w[2p+1][j]); j=27 zero
    __shared__ __align__(16) u64t sb2[128];
    const int t = threadIdx.x;

    if (t < 128) {
        const float* w0 = vw + (size_t)(2 * t) * 27;
        const float* w1 = w0 + 27;
#pragma unroll
        for (int j = 0; j < 27; j++) sw2[t][j] = pack2(w0[j], w1[j]);
        sw2[t][27] = pack2(0.f, 0.f);
        sb2[t] = pack2(vb[2 * t], vb[2 * t + 1]);
    }
    for (int i = t; i < CIN * 3 * 226; i += 256) {
        int ci = i / (3 * 226);
        int r  = (i / 226) % 3;
        int xx = i % 226;
        int yy = y + r - 1;
        int xc = xx - 1;
        float v = 0.f;
        if (yy >= 0 && yy < HW && xc >= 0 && xc < HW)
            v = x[(((size_t)b * CIN + ci) * HW + yy) * HW + xc];
        srow[ci][r][xx] = v;
    }
    __syncthreads();
    if (t >= HW) return;

    u64t xv2[28];
#pragma unroll
    for (int ci = 0; ci < CIN; ci++)
#pragma unroll
        for (int r = 0; r < 3; r++)
#pragma unroll
            for (int dx = 0; dx < 3; dx++) {
                float v = srow[ci][r][t + dx];
                xv2[(ci * 3 + r) * 3 + dx] = pack2(v, v);
            }
    xv2[27] = pack2(0.f, 0.f);

    const int hp = y >> 4, pi = y & 15;
    const int wp = t >> 4, pj = t & 15;
    const int n = hp * HP + wp;
#pragma unroll 1
    for (int h = 0; h < HEADS; h++) {
        const int bh = b * HEADS + h;
        __half* vout = g_vu + ((size_t)bh * NTOK + n) * DP + pi * PATCH + pj;
#pragma unroll 4
        for (int pp = 0; pp < 16; pp++) {
            const int pair = h * 16 + pp;
            u64t acc = sb2[pair];
#pragma unroll
            for (int j = 0; j < 28; j += 2) {
                ulonglong2 ww = *(const ulonglong2*)&sw2[pair][j];
                acc = fma2(xv2[j],     ww.x, acc);
                acc = fma2(xv2[j + 1], ww.y, acc);
            }
            float f0, f1;
            unpack2(acc, f0, f1);
            vout[(size_t)(2 * pp) * 256]       = __float2half(f0);
            vout[(size_t)(2 * pp) * 256 + 256] = __float2half(f1);
        }
    }
}

// == fp16 GEMM: m16n8k16, 128x128 tile, 256 thr (2 CTA/SM), 4-stage x 32k ====
// A smem: [128 m][20 words]  (16 data words = 32 halves k, 4 pad)
// B smem: [32 k][68 words]   (64 data words = 128 halves n, 4 pad)
#define STAGES  4
#define A_ST_W  2560        // 128*20
#define B_ST_W  2176        // 32*68
#define GEMM_SMEM (STAGES * (A_ST_W + B_ST_W) * 4)   // 75776 B

// one 16-k block of MMAs (kb_ in {0,16}); mmax_ = valid m extent within block
#define GEMM_KBLOCK(a_st_, b_st_, kb_, mmax_)                                 \
    do {                                                                      \
        uint32_t bf[4][2];                                                    \
        uint32_t bd0 = (b_st_) + (((kb_) * 68 + b_lane + wn * 16) << 2);      \
        ldsm_x4_t(bf[0][0], bf[0][1], bf[1][0], bf[1][1], bd0);               \
        ldsm_x4_t(bf[2][0], bf[2][1], bf[3][0], bf[3][1], bd0 + 32);          \
        _Pragma("unroll")                                                     \
        for (int mi = 0; mi < 4; mi++) {                                      \
            if (wm * 64 + mi * 16 < (mmax_)) {                                \
                uint32_t a0, a1, a2, a3;                                      \
                uint32_t ad = (a_st_) + (((wm * 64 + mi * 16) * 20 + ((kb_) >> 1) + a_lane) << 2); \
                ldsm_x4(a0, a1, a2, a3, ad);                                  \
                _Pragma("unroll")                                             \
                for (int ni = 0; ni < 4; ni++)                                \
                    mma_f16(acc[mi][ni], a0, a1, a2, a3, bf[ni][0], bf[ni][1]); \
            }                                                                 \
        }                                                                     \
    } while (0)

// ---------------- 4) attn @ vu -> pre ----------------------------------------
__global__ __launch_bounds__(256, 2) void gemm_attn_vu_f16() {
    extern __shared__ __align__(16) uint32_t dynw[];
    const uint32_t a_u32 = smem_u32(dynw);
    const uint32_t b_u32 = a_u32 + STAGES * A_ST_W * 4;

    const int bh = blockIdx.z;
    const int b = bh >> 3, h = bh & 7;
    const __half* __restrict__ Ah = g_attn + (size_t)bh * NTOK * AK;
    const __half* __restrict__ Bh = g_vu + (size_t)bh * NTOK * DP;
    const int row0 = blockIdx.y * 128;
    const int mmax = NTOK - row0;                 // valid m rows in this block
    const int col0 = blockIdx.x * 128;
    const int t = threadIdx.x;
    const int lane = t & 31, w = t >> 5;
    const int wm = w & 1, wn = w >> 1;
    const int fg = lane >> 2, ftg = lane & 3;
    const int a_lane = ((lane & 7) + ((lane >> 3) & 1) * 8) * 20 + ((lane >> 4) & 1) * 4;
    const int b_lane = ((lane & 7) + ((lane >> 3) & 1) * 8) * 68 + ((lane >> 4) & 1) * 4;
    const int arow = t >> 1, aq = (t & 1) * 2;    // A loader: 128 rows x 2 chunks/thr
    const int bkr = t >> 4, bnc = t & 15;         // B loader: rows bkr, bkr+16
    float acc[4][4][4] = {};

    // loader running state (advances kt -> kt+1 each issue)
    const int gm = row0 + arow;
    const bool pm = (gm < NTOK);
    const char* a_src = (const char*)Ah + gm * (AK * 2) + aq * 16;
    int akoff = aq * 16;                          // byte k-offset within A row
    const __half* b_src = Bh + (size_t)bkr * DP + col0 + bnc * 8;
    int gk = bkr;                                 // global k row of first B chunk
    const uint32_t ad_base = a_u32 + (arow * 20 + aq * 4) * 4;
    const uint32_t bd_base = b_u32 + (bkr * 68 + bnc * 4) * 4;

    auto issue = [&](int st) {
        uint32_t ad = ad_base + st * (A_ST_W * 4);
        cp16(ad,      a_src,      pm && akoff < AK * 2);
        cp16(ad + 16, a_src + 16, pm && akoff + 16 < AK * 2);
        uint32_t bd = bd_base + st * (B_ST_W * 4);
        cp16(bd,               b_src,           gk < NTOK);
        cp16(bd + 16 * 68 * 4, b_src + 16 * DP, gk + 16 < NTOK);
        a_src += 64; akoff += 64;
        b_src += 32 * DP; gk += 32;
    };

    const int NK = 7;   // ceil(196/32)
#pragma unroll
    for (int p = 0; p < STAGES - 1; p++) { issue(p); CP_COMMIT(); }
    CP_WAIT2();
    __syncthreads();
#pragma unroll 1
    for (int it = 0; it < NK; it++) {
        int pf = it + STAGES - 1;
        if (pf < NK) issue(pf & 3);
        CP_COMMIT();
        uint32_t a_st = a_u32 + (it & 3) * A_ST_W * 4;
        uint32_t b_st = b_u32 + (it & 3) * B_ST_W * 4;
        GEMM_KBLOCK(a_st, b_st, 0, mmax);
        GEMM_KBLOCK(a_st, b_st, 16, mmax);
        CP_WAIT2();
        __syncthreads();
    }

    // epilogue: fold-scatter into fp16 NCHW pre (__half2 per dp-pair)
#pragma unroll
    for (int mi = 0; mi < 4; mi++) {
#pragma unroll
        for (int half = 0; half < 2; half++) {
            int m = row0 + wm * 64 + mi * 16 + fg + half * 8;
            if (m >= NTOK) continue;
            int hp = m / HP, wp = m % HP;
#pragma unroll
            for (int ni = 0; ni < 4; ni++) {
                int dp = col0 + wn * 32 + ni * 8 + ftg * 2;
                int cr = dp >> 8, rem = dp & 255;
                int pi = rem >> 4, pj = rem & 15;
                int c = h * 32 + cr;
                int pix = (hp * PATCH + pi) * HW + wp * PATCH + pj;
                __half2 v = __floats2half2_rn(acc[mi][ni][half * 2 + 0],
                                              acc[mi][ni][half * 2 + 1]);
                *(__half2*)&g_pre[((size_t)b * DIM + c) * PIX + pix] = v;
            }
        }
    }
}

// ---------------- 5) 1x1 proj -------------------------------------------------
__global__ __launch_bounds__(256, 2) void gemm_proj_f16(
        const float* __restrict__ pb,
        float* __restrict__ out) {
    extern __shared__ __align__(16) uint32_t dynw[];
    const uint32_t a_u32 = smem_u32(dynw);
    const uint32_t b_u32 = a_u32 + STAGES * A_ST_W * 4;

    const int b = blockIdx.z;
    const __half* __restrict__ Bh = g_pre + (size_t)b * DIM * PIX;
    float* __restrict__ C = out + (size_t)b * DIM * PIX;
    const int row0 = blockIdx.y * 128;
    const int col0 = blockIdx.x * 128;
    const int t = threadIdx.x;
    const int lane = t & 31, w = t >> 5;
    const int wm = w & 1, wn = w >> 1;
    const int fg = lane >> 2, ftg = lane & 3;
    const int a_lane = ((lane & 7) + ((lane >> 3) & 1) * 8) * 20 + ((lane >> 4) & 1) * 4;
    const int b_lane = ((lane & 7) + ((lane >> 3) & 1) * 8) * 68 + ((lane >> 4) & 1) * 4;
    const int arow = t >> 1, aq = (t & 1) * 2;
    const int bkr = t >> 4, bnc = t & 15;
    float acc[4][4][4] = {};

    const char* a_src = (const char*)g_pw + (row0 + arow) * (DIM * 2) + aq * 16;
    const __half* b_src = Bh + (size_t)bkr * PIX + col0 + bnc * 8;
    const uint32_t ad_base = a_u32 + (arow * 20 + aq * 4) * 4;
    const uint32_t bd_base = b_u32 + (bkr * 68 + bnc * 4) * 4;

    auto issue = [&](int st) {
        uint32_t ad = ad_base + st * (A_ST_W * 4);
        cp16(ad,      a_src,      true);
        cp16(ad + 16, a_src + 16, true);
        uint32_t bd = bd_base + st * (B_ST_W * 4);
        cp16(bd,               b_src,           true);
        cp16(bd + 16 * 68 * 4, b_src + 16 * PIX, true);
        a_src += 64;
        b_src += 32 * PIX;
    };

    const int NK = 8;   // 256/32
#pragma unroll
    for (int p = 0; p < STAGES - 1; p++) { issue(p); CP_COMMIT(); }
    CP_WAIT2();
    __syncthreads();
#pragma unroll 1
    for (int it = 0; it < NK; it++) {
        int pf = it + STAGES - 1;
        if (pf < NK) issue(pf & 3);
        CP_COMMIT();
        uint32_t a_st = a_u32 + (it & 3) * A_ST_W * 4;
        uint32_t b_st = b_u32 + (it & 3) * B_ST_W * 4;
        GEMM_KBLOCK(a_st, b_st, 0, 128);
        GEMM_KBLOCK(a_st, b_st, 16, 128);
        CP_WAIT2();
        __syncthreads();
    }

#pragma unroll
    for (int mi = 0; mi < 4; mi++) {
#pragma unroll
        for (int half = 0; half < 2; half++) {
            int co = row0 + wm * 64 + mi * 16 + fg + half * 8;
            float bias = pb[co];
            float* crow = &C[(size_t)co * PIX + col0 + wn * 32 + ftg * 2];
#pragma unroll
            for (int ni = 0; ni < 4; ni++) {
                float2 v = make_float2(acc[mi][ni][half * 2 + 0] + bias,
                                       acc[mi][ni][half * 2 + 1] + bias);
                *(float2*)&crow[ni * 8] = v;
            }
        }
    }
}

// ---------------- launch -----------------------------------------------------
extern "C" void kernel_launch(void* const* d_in, const int* in_sizes, int n_in,
                              void* d_out, int out_size) {
    const float* x       = (const float*)d_in[0];
    const float* patch_w = (const float*)d_in[1];
    const float* patch_b = (const float*)d_in[2];
    const float* qk_w    = (const float*)d_in[3];
    const float* v_w     = (const float*)d_in[4];
    const float* v_b     = (const float*)d_in[5];
    const float* proj_w  = (const float*)d_in[6];
    const float* proj_b  = (const float*)d_in[7];
    float* out = (float*)d_out;

    cudaFuncSetAttribute(gemm_attn_vu_f16,
                         cudaFuncAttributeMaxDynamicSharedMemorySize, GEMM_SMEM);
    cudaFuncSetAttribute(gemm_proj_f16,
                         cudaFuncAttributeMaxDynamicSharedMemorySize, GEMM_SMEM);

    patchqk16<<<BATCH * NTOK / 8, 256>>>(x, patch_w, patch_b, qk_w);
    softmax_v2<<<BATCH * HEADS, 256>>>();
    convv_unfold_kernel<<<dim3(HW, BATCH), 256>>>(x, v_w, v_b);
    gemm_attn_vu_f16<<<dim3(DP / 128, 2, BATCH * HEADS), 256, GEMM_SMEM>>>();
    cvt_pw_kernel<<<DIM * DIM / 256, 256>>>(proj_w);
    gemm_proj_f16<<<dim3(PIX / 128, 2, BATCH), 256, GEMM_SMEM>>>(proj_b, out);
}

// round 16
// speedup vs baseline: 1.1500x; 1.1500x over previous
#include <cuda_runtime.h>
#include <cuda_fp16.h>
#include <math.h>
#include <cstdint>

// Problem constants
#define BATCH 4
#define CIN   3
#define HW    224
#define PATCH 16
#define DIM   256
#define HEADS 8
#define HD    32
#define HP    14
#define NTOK  196
#define DP    8192
#define PIX   50176
#define AK    208          // padded k-stride for g_attn rows (halves), zero-filled

// ---------------- scratch (device globals) ----------------------------------
__device__ __align__(16) float  g_q[BATCH * HEADS * NTOK * HD];
__device__ __align__(16) float  g_k[BATCH * HEADS * NTOK * HD];
__device__ __align__(16) __half g_attn[(size_t)BATCH * HEADS * NTOK * AK];   // [n][k]
__device__ __align__(16) __half g_vu[(size_t)BATCH * HEADS * NTOK * DP];     // [m][d']
__device__ __align__(16) __half g_pre[(size_t)BATCH * DIM * PIX];            // [c][pix]
__device__ __align__(16) __half g_pw[DIM * DIM];                             // [co][c]
__device__ __align__(16) __half g_ic[(size_t)BATCH * 32 * PIX];              // im2col [b][k32][pix]
__device__ __align__(16) __half g_cw[DIM * 32];                              // conv w [co][k32]

__device__ __forceinline__ uint32_t smem_u32(const void* p) {
    uint32_t a;
    asm("{ .reg .u64 t; cvta.to.shared.u64 t, %1; cvt.u32.u64 %0, t; }" : "=r"(a) : "l"(p));
    return a;
}
__device__ __forceinline__ void mma_f16(float d[4],
        uint32_t a0, uint32_t a1, uint32_t a2, uint32_t a3,
        uint32_t b0, uint32_t b1) {
    asm volatile(
        "mma.sync.aligned.m16n8k16.row.col.f32.f16.f16.f32 "
        "{%0,%1,%2,%3}, {%4,%5,%6,%7}, {%8,%9}, {%0,%1,%2,%3};"
        : "+f"(d[0]), "+f"(d[1]), "+f"(d[2]), "+f"(d[3])
        : "r"(a0), "r"(a1), "r"(a2), "r"(a3), "r"(b0), "r"(b1));
}
__device__ __forceinline__ void ldsm_x4(uint32_t& r0, uint32_t& r1,
                                        uint32_t& r2, uint32_t& r3, uint32_t addr) {
    asm volatile("ldmatrix.sync.aligned.m8n8.x4.shared.b16 {%0,%1,%2,%3}, [%4];"
                 : "=r"(r0), "=r"(r1), "=r"(r2), "=r"(r3) : "r"(addr));
}
__device__ __forceinline__ void ldsm_x4_t(uint32_t& r0, uint32_t& r1,
                                          uint32_t& r2, uint32_t& r3, uint32_t addr) {
    asm volatile("ldmatrix.sync.aligned.m8n8.x4.trans.shared.b16 {%0,%1,%2,%3}, [%4];"
                 : "=r"(r0), "=r"(r1), "=r"(r2), "=r"(r3) : "r"(addr));
}
__device__ __forceinline__ void cp16(uint32_t dst, const void* src, bool pred) {
    asm volatile("cp.async.cg.shared.global [%0], [%1], 16, %2;"
                 :: "r"(dst), "l"(src), "r"(pred ? 16 : 0) : "memory");
}
#define CP_COMMIT() asm volatile("cp.async.commit_group;" ::: "memory")
#define CP_WAIT2()  asm volatile("cp.async.wait_group 2;" ::: "memory")
#define CP_WAIT0()  asm volatile("cp.async.wait_group 0;" ::: "memory")

// ---------------- 0) weight conversions --------------------------------------
__global__ void cvt_pw_kernel(const float* __restrict__ pw) {
    int i = blockIdx.x * 256 + threadIdx.x;
    g_pw[i] = __float2half(pw[i]);
}
__global__ void cvt_vw_kernel(const float* __restrict__ vw) {
    int co = threadIdx.x;   // 256
#pragma unroll
    for (int j = 0; j < 27; j++) g_cw[co * 32 + j] = __float2half(vw[co * 27 + j]);
#pragma unroll
    for (int j = 27; j < 32; j++) g_cw[co * 32 + j] = __float2half(0.f);
}

// ---------------- 1) fused patch embed + qk ----------------------------------
__global__ __launch_bounds__(256) void patchqk16(const float* __restrict__ x,
                                                 const float* __restrict__ w,
                                                 const float* __restrict__ bias,
                                                 const float* __restrict__ qkw) {
    const int bn0 = blockIdx.x * 8;
    __shared__ __align__(16) float sp[8][768];
    __shared__ __align__(16) float sx[8][256];
    for (int idx = threadIdx.x; idx < 8 * 768; idx += 256) {
        int i = idx / 768, j = idx - (idx / 768) * 768;
        int bn = bn0 + i;
        int b = bn / NTOK, n = bn % NTOK;
        int hp = n / HP, wp = n % HP;
        int ci = j >> 8, r = (j >> 4) & 15, cc = j & 15;
        sp[i][j] = x[(((size_t)b * CIN + ci) * HW + hp * PATCH + r) * HW + wp * PATCH + cc];
    }
    __syncthreads();
    const int co = threadIdx.x;
    {
        const float4* wr = (const float4*)(w + (size_t)co * 768);
        float acc[8] = {};
#pragma unroll 2
        for (int j4 = 0; j4 < 192; j4++) {
            float4 w4 = wr[j4];
#pragma unroll
            for (int i = 0; i < 8; i++) {
                float4 s4 = *(const float4*)&sp[i][j4 * 4];
                acc[i] = fmaf(s4.x, w4.x, fmaf(s4.y, w4.y, fmaf(s4.z, w4.z, fmaf(s4.w, w4.w, acc[i]))));
            }
        }
        float bco = bias[co];
#pragma unroll
        for (int i = 0; i < 8; i++) sx[i][co] = acc[i] + bco;
    }
    __syncthreads();
    {
        const float4* w0 = (const float4*)(qkw + (size_t)co * DIM);
        const float4* w1 = (const float4*)(qkw + (size_t)(DIM + co) * DIM);
        float acc0[8] = {}, acc1[8] = {};
#pragma unroll 2
        for (int j4 = 0; j4 < 64; j4++) {
            float4 a = w0[j4];
            float4 bq = w1[j4];
#pragma unroll
            for (int i = 0; i < 8; i++) {
                float4 s4 = *(const float4*)&sx[i][j4 * 4];
                acc0[i] = fmaf(s4.x, a.x,  fmaf(s4.y, a.y,  fmaf(s4.z, a.z,  fmaf(s4.w, a.w,  acc0[i]))));
                acc1[i] = fmaf(s4.x, bq.x, fmaf(s4.y, bq.y, fmaf(s4.z, bq.z, fmaf(s4.w, bq.w, acc1[i]))));
            }
        }
        const int h = co >> 5, d = co & 31;
#pragma unroll
        for (int i = 0; i < 8; i++) {
            int bn = bn0 + i;
            int b = bn / NTOK, n = bn % NTOK;
            size_t off = (((size_t)b * HEADS + h) * NTOK + n) * HD + d;
            g_q[off] = acc0[i];
            g_k[off] = acc1[i];
        }
    }
}

// ---------------- 2) scores + softmax -> attn (fp16, pad zeroed) -------------
__global__ __launch_bounds__(256) void softmax_v2() {
    const int bh = blockIdx.x;
    __shared__ float sk[NTOK][33];
    const float* kb = g_k + (size_t)bh * NTOK * HD;
    for (int i = threadIdx.x; i < NTOK * HD; i += 256)
        sk[i >> 5][i & 31] = kb[i];
    __syncthreads();
    const int wid = threadIdx.x >> 5, lane = threadIdx.x & 31;
    for (int n = wid; n < NTOK; n += 8) {
        float qd = g_q[((size_t)bh * NTOK + n) * HD + lane];
        float acc[7] = {};
#pragma unroll
        for (int d = 0; d < HD; d++) {
            float qv = __shfl_sync(0xffffffffu, qd, d);
#pragma unroll
            for (int j = 0; j < 7; j++) {
                int m = j * 32 + lane;
                int mc = m < NTOK ? m : NTOK - 1;
                acc[j] = fmaf(qv, sk[mc][d], acc[j]);
            }
        }
        float sc[7], mx = -INFINITY;
#pragma unroll
        for (int j = 0; j < 7; j++) {
            int m = j * 32 + lane;
            sc[j] = (m < NTOK) ? acc[j] * 0.17677669529663687f : -INFINITY;
            mx = fmaxf(mx, sc[j]);
        }
#pragma unroll
        for (int off = 16; off > 0; off >>= 1)
            mx = fmaxf(mx, __shfl_xor_sync(0xffffffffu, mx, off));
        float sum = 0.f;
#pragma unroll
        for (int j = 0; j < 7; j++) {
            sc[j] = expf(sc[j] - mx);
            sum += sc[j];
        }
#pragma unroll
        for (int off = 16; off > 0; off >>= 1)
            sum += __shfl_xor_sync(0xffffffffu, sum, off);
        float inv = 1.f / sum;
        __half* arow = g_attn + ((size_t)bh * NTOK + n) * AK;
#pragma unroll
        for (int j = 0; j < 7; j++) {
            int m = j * 32 + lane;
            if (m < NTOK)      arow[m] = __float2half(sc[j] * inv);
            else if (m < AK)   arow[m] = __float2half(0.f);
        }
    }
}

// ---------------- 3a) im2col: x -> g_ic[b][32][pix] (fp16) -------------------
__global__ __launch_bounds__(224) void im2col_kernel(const float* __restrict__ x) {
    const int y = blockIdx.x;      // 224
    const int krow = blockIdx.y;   // 32
    const int b = blockIdx.z;      // 4
    const int xx = threadIdx.x;    // 224
    float v = 0.f;
    if (krow < 27) {
        int ci = krow / 9;
        int rr = (krow / 3) % 3;
        int dxx = krow % 3;
        int yy = y + rr - 1, xc = xx + dxx - 1;
        if (yy >= 0 && yy < HW && xc >= 0 && xc < HW)
            v = x[(((size_t)b * CIN + ci) * HW + yy) * HW + xc];
    }
    g_ic[((size_t)b * 32 + krow) * PIX + y * HW + xx] = __float2half(v);
}

// == fp16 GEMM machinery: m16n8k16, 128x128 tile, 256 thr, ldmatrix ==========
// A smem: [128 m][20 words]  (16 data words = 32 halves k, 4 pad)
// B smem: [32 k][68 words]   (64 data words = 128 halves n, 4 pad)
#define STAGES  4
#define A_ST_W  2560        // 128*20
#define B_ST_W  2176        // 32*68
#define GEMM_SMEM (STAGES * (A_ST_W + B_ST_W) * 4)   // 75776 B

// one 16-k block of MMAs (kb_ in {0,16}); 8 warps: wm = w&1, wn = w>>1
#define GEMM_KBLOCK(a_st_, b_st_, kb_)                                        \
    do {                                                                      \
        uint32_t af[4][4], bf[4][2];                                          \
        _Pragma("unroll")                                                     \
        for (int mi = 0; mi < 4; mi++) {                                      \
            uint32_t ad = (a_st_) + (((wm * 64 + mi * 16) * 20 + ((kb_) >> 1) + a_lane) << 2); \
            ldsm_x4(af[mi][0], af[mi][1], af[mi][2], af[mi][3], ad);          \
        }                                                                     \
        {                                                                     \
            uint32_t bd0 = (b_st_) + (((kb_) * 68 + b_lane + wn * 16) << 2);  \
            ldsm_x4_t(bf[0][0], bf[0][1], bf[1][0], bf[1][1], bd0);           \
            ldsm_x4_t(bf[2][0], bf[2][1], bf[3][0], bf[3][1], bd0 + 32);      \
        }                                                                     \
        _Pragma("unroll")                                                     \
        for (int mi = 0; mi < 4; mi++)                                        \
            _Pragma("unroll")                                                 \
            for (int ni = 0; ni < 4; ni++)                                    \
                mma_f16(acc[mi][ni], af[mi][0], af[mi][1], af[mi][2],         \
                        af[mi][3], bf[ni][0], bf[ni][1]);                     \
    } while (0)

// ---------------- 3b) conv GEMM: g_cw @ g_ic -> g_vu (fused unfold + bias) ---
// per batch: C[256ch, PIX] , K=32 single tile
__global__ __launch_bounds__(256) void gemm_conv_f16(const float* __restrict__ vb) {
    __shared__ __align__(16) uint32_t sA[A_ST_W];
    __shared__ __align__(16) uint32_t sB[B_ST_W];
    const uint32_t a_st = smem_u32(sA);
    const uint32_t b_st = smem_u32(sB);

    const int b = blockIdx.z;
    const int row0 = blockIdx.y * 128;   // channel block
    const int col0 = blockIdx.x * 128;   // pixel block
    const int t = threadIdx.x;
    const int lane = t & 31, w = t >> 5;
    const int wm = w & 1, wn = w >> 1;
    const int fg = lane >> 2, ftg = lane & 3;
    const int a_lane = ((lane & 7) + ((lane >> 3) & 1) * 8) * 20 + ((lane >> 4) & 1) * 4;
    const int b_lane = ((lane & 7) + ((lane >> 3) & 1) * 8) * 68 + ((lane >> 4) & 1) * 4;
    float acc[4][4][4] = {};

    {   // single-shot loads
        int arow = t >> 1, aq = (t & 1) * 2;
        uint32_t ad = a_st + (arow * 20 + aq * 4) * 4;
        const char* asrc = (const char*)g_cw + (row0 + arow) * 64 + aq * 16;
        cp16(ad,      asrc,      true);
        cp16(ad + 16, asrc + 16, true);
        int bkr = t >> 4, bnc = t & 15;
        uint32_t bd = b_st + (bkr * 68 + bnc * 4) * 4;
        const __half* bsrc = g_ic + ((size_t)b * 32 + bkr) * PIX + col0 + bnc * 8;
        cp16(bd,               bsrc,            true);
        cp16(bd + 16 * 68 * 4, bsrc + 16 * PIX, true);
    }
    CP_COMMIT();
    CP_WAIT0();
    __syncthreads();

    GEMM_KBLOCK(a_st, b_st, 0);
    GEMM_KBLOCK(a_st, b_st, 16);

    // epilogue: bias + scatter into unfolded g_vu layout
#pragma unroll
    for (int mi = 0; mi < 4; mi++) {
#pragma unroll
        for (int half = 0; half < 2; half++) {
            int co = row0 + wm * 64 + mi * 16 + fg + half * 8;
            float bias = vb[co];
            int h = co >> 5, cr = co & 31;
            const int bh = b * HEADS + h;
#pragma unroll
            for (int ni = 0; ni < 4; ni++) {
                int pix = col0 + wn * 32 + ni * 8 + ftg * 2;
                int yy = pix / HW, xx = pix - (pix / HW) * HW;   // xx even -> pair intra-patch
                int n = (yy >> 4) * HP + (xx >> 4);
                int dp = cr * 256 + (yy & 15) * PATCH + (xx & 15);
                __half2 v = __floats2half2_rn(acc[mi][ni][half * 2 + 0] + bias,
                                              acc[mi][ni][half * 2 + 1] + bias);
                *(__half2*)&g_vu[((size_t)bh * NTOK + n) * DP + dp] = v;
            }
        }
    }
}

// ---------------- 4) attn @ vu -> pre (exact R12) -----------------------------
__global__ __launch_bounds__(256, 2) void gemm_attn_vu_f16() {
    extern __shared__ __align__(16) uint32_t dynw[];
    const uint32_t a_u32 = smem_u32(dynw);
    const uint32_t b_u32 = a_u32 + STAGES * A_ST_W * 4;

    const int bh = blockIdx.z;
    const int b = bh >> 3, h = bh & 7;
    const __half* __restrict__ Ah = g_attn + (size_t)bh * NTOK * AK;
    const __half* __restrict__ Bh = g_vu + (size_t)bh * NTOK * DP;
    const int row0 = blockIdx.y * 128;
    const int col0 = blockIdx.x * 128;
    const int t = threadIdx.x;
    const int lane = t & 31, w = t >> 5;
    const int wm = w & 1, wn = w >> 1;
    const int fg = lane >> 2, ftg = lane & 3;
    const int a_lane = ((lane & 7) + ((lane >> 3) & 1) * 8) * 20 + ((lane >> 4) & 1) * 4;
    const int b_lane = ((lane & 7) + ((lane >> 3) & 1) * 8) * 68 + ((lane >> 4) & 1) * 4;
    const int arow = t >> 1, aq = (t & 1) * 2;
    const int bkr = t >> 4, bnc = t & 15;
    float acc[4][4][4] = {};

#define AVU_ISSUE(st_, kt_)                                                   \
    do {                                                                      \
        int gm = row0 + arow;                                                 \
        uint32_t ad = a_u32 + ((st_) * A_ST_W + arow * 20 + aq * 4) * 4;      \
        const char* asrc = (const char*)Ah + gm * (AK * 2) + (kt_) * 64 + aq * 16; \
        bool pm = (gm < NTOK);                                                \
        cp16(ad,      asrc,      pm && ((kt_) * 64 + aq * 16)      < AK * 2); \
        cp16(ad + 16, asrc + 16, pm && ((kt_) * 64 + aq * 16 + 16) < AK * 2); \
        int gk0 = (kt_) * 32 + bkr;                                           \
        int gk1 = gk0 + 16;                                                   \
        uint32_t bd = b_u32 + ((st_) * B_ST_W + bkr * 68 + bnc * 4) * 4;      \
        cp16(bd, Bh + (size_t)gk0 * DP + col0 + bnc * 8, gk0 < NTOK);         \
        cp16(bd + 16 * 68 * 4, Bh + (size_t)gk1 * DP + col0 + bnc * 8, gk1 < NTOK); \
    } while (0)

    const int NK = 7;   // ceil(196/32)
#pragma unroll
    for (int p = 0; p < STAGES - 1; p++) { AVU_ISSUE(p, p); CP_COMMIT(); }
    CP_WAIT2();
    __syncthreads();
#pragma unroll 1
    for (int it = 0; it < NK; it++) {
        int pf = it + STAGES - 1;
        if (pf < NK) AVU_ISSUE(pf & 3, pf);
        CP_COMMIT();
        uint32_t a_st = a_u32 + (it & 3) * A_ST_W * 4;
        uint32_t b_st = b_u32 + (it & 3) * B_ST_W * 4;
        GEMM_KBLOCK(a_st, b_st, 0);
        GEMM_KBLOCK(a_st, b_st, 16);
        CP_WAIT2();
        __syncthreads();
    }
#undef AVU_ISSUE

    // epilogue: fold-scatter into fp16 NCHW pre (__half2 per dp-pair)
#pragma unroll
    for (int mi = 0; mi < 4; mi++) {
#pragma unroll
        for (int half = 0; half < 2; half++) {
            int m = row0 + wm * 64 + mi * 16 + fg + half * 8;
            if (m >= NTOK) continue;
            int hp = m / HP, wp = m % HP;
#pragma unroll
            for (int ni = 0; ni < 4; ni++) {
                int dp = col0 + wn * 32 + ni * 8 + ftg * 2;
                int cr = dp >> 8, rem = dp & 255;
                int pi = rem >> 4, pj = rem & 15;
                int c = h * 32 + cr;
                int pix = (hp * PATCH + pi) * HW + wp * PATCH + pj;
                __half2 v = __floats2half2_rn(acc[mi][ni][half * 2 + 0],
                                              acc[mi][ni][half * 2 + 1]);
                *(__half2*)&g_pre[((size_t)b * DIM + c) * PIX + pix] = v;
            }
        }
    }
}

// ---------------- 5) 1x1 proj (exact R12) --------------------------------------
__global__ __launch_bounds__(256, 2) void gemm_proj_f16(
        const float* __restrict__ pb,
        float* __restrict__ out) {
    extern __shared__ __align__(16) uint32_t dynw[];
    const uint32_t a_u32 = smem_u32(dynw);
    const uint32_t b_u32 = a_u32 + STAGES * A_ST_W * 4;

    const int b = blockIdx.z;
    const __half* __restrict__ Bh = g_pre + (size_t)b * DIM * PIX;
    float* __restrict__ C = out + (size_t)b * DIM * PIX;
    const int row0 = blockIdx.y * 128;
    const int col0 = blockIdx.x * 128;
    const int t = threadIdx.x;
    const int lane = t & 31, w = t >> 5;
    const int wm = w & 1, wn = w >> 1;
    const int fg = lane >> 2, ftg = lane & 3;
    const int a_lane = ((lane & 7) + ((lane >> 3) & 1) * 8) * 20 + ((lane >> 4) & 1) * 4;
    const int b_lane = ((lane & 7) + ((lane >> 3) & 1) * 8) * 68 + ((lane >> 4) & 1) * 4;
    const int arow = t >> 1, aq = (t & 1) * 2;
    const int bkr = t >> 4, bnc = t & 15;
    float acc[4][4][4] = {};

#define PROJ_ISSUE(st_, kt_)                                                  \
    do {                                                                      \
        uint32_t ad = a_u32 + ((st_) * A_ST_W + arow * 20 + aq * 4) * 4;      \
        const char* asrc = (const char*)g_pw + (row0 + arow) * (DIM * 2) + (kt_) * 64 + aq * 16; \
        cp16(ad,      asrc,      true);                                       \
        cp16(ad + 16, asrc + 16, true);                                       \
        int gk0 = (kt_) * 32 + bkr;                                           \
        uint32_t bd = b_u32 + ((st_) * B_ST_W + bkr * 68 + bnc * 4) * 4;      \
        cp16(bd, Bh + (size_t)gk0 * PIX + col0 + bnc * 8, true);              \
        cp16(bd + 16 * 68 * 4, Bh + (size_t)(gk0 + 16) * PIX + col0 + bnc * 8, true); \
    } while (0)

    const int NK = 8;   // 256/32
#pragma unroll
    for (int p = 0; p < STAGES - 1; p++) { PROJ_ISSUE(p, p); CP_COMMIT(); }
    CP_WAIT2();
    __syncthreads();
#pragma unroll 1
    for (int it = 0; it < NK; it++) {
        int pf = it + STAGES - 1;
        if (pf < NK) PROJ_ISSUE(pf & 3, pf);
        CP_COMMIT();
        uint32_t a_st = a_u32 + (it & 3) * A_ST_W * 4;
        uint32_t b_st = b_u32 + (it & 3) * B_ST_W * 4;
        GEMM_KBLOCK(a_st, b_st, 0);
        GEMM_KBLOCK(a_st, b_st, 16);
        CP_WAIT2();
        __syncthreads();
    }
#undef PROJ_ISSUE

#pragma unroll
    for (int mi = 0; mi < 4; mi++) {
#pragma unroll
        for (int half = 0; half < 2; half++) {
            int co = row0 + wm * 64 + mi * 16 + fg + half * 8;
            float bias = pb[co];
            float* crow = &C[(size_t)co * PIX + col0 + wn * 32 + ftg * 2];
#pragma unroll
            for (int ni = 0; ni < 4; ni++) {
                float2 v = make_float2(acc[mi][ni][half * 2 + 0] + bias,
                                       acc[mi][ni][half * 2 + 1] + bias);
                *(float2*)&crow[ni * 8] = v;
            }
        }
    }
}

// ---------------- launch -----------------------------------------------------
extern "C" void kernel_launch(void* const* d_in, const int* in_sizes, int n_in,
                              void* d_out, int out_size) {
    const float* x       = (const float*)d_in[0];
    const float* patch_w = (const float*)d_in[1];
    const float* patch_b = (const float*)d_in[2];
    const float* qk_w    = (const float*)d_in[3];
    const float* v_w     = (const float*)d_in[4];
    const float* v_b     = (const float*)d_in[5];
    const float* proj_w  = (const float*)d_in[6];
    const float* proj_b  = (const float*)d_in[7];
    float* out = (float*)d_out;

    cudaFuncSetAttribute(gemm_attn_vu_f16,
                         cudaFuncAttributeMaxDynamicSharedMemorySize, GEMM_SMEM);
    cudaFuncSetAttribute(gemm_proj_f16,
                         cudaFuncAttributeMaxDynamicSharedMemorySize, GEMM_SMEM);

    patchqk16<<<BATCH * NTOK / 8, 256>>>(x, patch_w, patch_b, qk_w);
    softmax_v2<<<BATCH * HEADS, 256>>>();
    im2col_kernel<<<dim3(HW, 32, BATCH), 224>>>(x);
    cvt_vw_kernel<<<1, 256>>>(v_w);
    gemm_conv_f16<<<dim3(PIX / 128, 2, BATCH), 256>>>(v_b);
    gemm_attn_vu_f16<<<dim3(DP / 128, 2, BATCH * HEADS), 256, GEMM_SMEM>>>();
    cvt_pw_kernel<<<DIM * DIM / 256, 256>>>(proj_w);
    gemm_proj_f16<<<dim3(PIX / 128, 2, BATCH), 256, GEMM_SMEM>>>(proj_b, out);
}

// round 17
// speedup vs baseline: 1.1643x; 1.0125x over previous
#include <cuda_runtime.h>
#include <cuda_fp16.h>
#include <math.h>
#include <cstdint>

// Problem constants
#define BATCH 4
#define CIN   3
#define HW    224
#define PATCH 16
#define DIM   256
#define HEADS 8
#define HD    32
#define HP    14
#define NTOK  196
#define DP    8192
#define PIX   50176
#define AK    208          // padded k-stride for g_attn rows (halves), zero-filled

// ---------------- scratch (device globals) ----------------------------------
__device__ __align__(16) float  g_q[BATCH * HEADS * NTOK * HD];
__device__ __align__(16) float  g_k[BATCH * HEADS * NTOK * HD];
__device__ __align__(16) __half g_attn[(size_t)BATCH * HEADS * NTOK * AK];   // [n][k]
__device__ __align__(16) __half g_vu[(size_t)BATCH * HEADS * NTOK * DP];     // [m][d']
__device__ __align__(16) __half g_pre[(size_t)BATCH * DIM * PIX];            // [c][pix]
__device__ __align__(16) __half g_pw[DIM * DIM];                             // [co][c]
__device__ __align__(16) __half g_ic[(size_t)BATCH * 32 * PIX];              // im2col [b][k32][pix]
__device__ __align__(16) __half g_cw[DIM * 32];                              // conv w [co][k32]

__device__ __forceinline__ uint32_t smem_u32(const void* p) {
    uint32_t a;
    asm("{ .reg .u64 t; cvta.to.shared.u64 t, %1; cvt.u32.u64 %0, t; }" : "=r"(a) : "l"(p));
    return a;
}
__device__ __forceinline__ void mma_f16(float d[4],
        uint32_t a0, uint32_t a1, uint32_t a2, uint32_t a3,
        uint32_t b0, uint32_t b1) {
    asm volatile(
        "mma.sync.aligned.m16n8k16.row.col.f32.f16.f16.f32 "
        "{%0,%1,%2,%3}, {%4,%5,%6,%7}, {%8,%9}, {%0,%1,%2,%3};"
        : "+f"(d[0]), "+f"(d[1]), "+f"(d[2]), "+f"(d[3])
        : "r"(a0), "r"(a1), "r"(a2), "r"(a3), "r"(b0), "r"(b1));
}
__device__ __forceinline__ void ldsm_x4(uint32_t& r0, uint32_t& r1,
                                        uint32_t& r2, uint32_t& r3, uint32_t addr) {
    asm volatile("ldmatrix.sync.aligned.m8n8.x4.shared.b16 {%0,%1,%2,%3}, [%4];"
                 : "=r"(r0), "=r"(r1), "=r"(r2), "=r"(r3) : "r"(addr));
}
__device__ __forceinline__ void ldsm_x4_t(uint32_t& r0, uint32_t& r1,
                                          uint32_t& r2, uint32_t& r3, uint32_t addr) {
    asm volatile("ldmatrix.sync.aligned.m8n8.x4.trans.shared.b16 {%0,%1,%2,%3}, [%4];"
                 : "=r"(r0), "=r"(r1), "=r"(r2), "=r"(r3) : "r"(addr));
}
__device__ __forceinline__ void cp16(uint32_t dst, const void* src, bool pred) {
    asm volatile("cp.async.cg.shared.global [%0], [%1], 16, %2;"
                 :: "r"(dst), "l"(src), "r"(pred ? 16 : 0) : "memory");
}
#define CP_COMMIT() asm volatile("cp.async.commit_group;" ::: "memory")
#define CP_WAIT2()  asm volatile("cp.async.wait_group 2;" ::: "memory")
#define CP_WAIT0()  asm volatile("cp.async.wait_group 0;" ::: "memory")

// ---------------- 0) weight conversions --------------------------------------
__global__ void cvt_pw_kernel(const float* __restrict__ pw) {
    int i = blockIdx.x * 256 + threadIdx.x;
    g_pw[i] = __float2half(pw[i]);
}
__global__ void cvt_vw_kernel(const float* __restrict__ vw) {
    int co = threadIdx.x;   // 256
#pragma unroll
    for (int j = 0; j < 27; j++) g_cw[co * 32 + j] = __float2half(vw[co * 27 + j]);
#pragma unroll
    for (int j = 27; j < 32; j++) g_cw[co * 32 + j] = __float2half(0.f);
}

// ---------------- 1) fused patch embed + qk ----------------------------------
__global__ __launch_bounds__(256) void patchqk16(const float* __restrict__ x,
                                                 const float* __restrict__ w,
                                                 const float* __restrict__ bias,
                                                 const float* __restrict__ qkw) {
    const int bn0 = blockIdx.x * 8;
    __shared__ __align__(16) float sp[8][768];
    __shared__ __align__(16) float sx[8][256];
    for (int idx = threadIdx.x; idx < 8 * 768; idx += 256) {
        int i = idx / 768, j = idx - (idx / 768) * 768;
        int bn = bn0 + i;
        int b = bn / NTOK, n = bn % NTOK;
        int hp = n / HP, wp = n % HP;
        int ci = j >> 8, r = (j >> 4) & 15, cc = j & 15;
        sp[i][j] = x[(((size_t)b * CIN + ci) * HW + hp * PATCH + r) * HW + wp * PATCH + cc];
    }
    __syncthreads();
    const int co = threadIdx.x;
    {
        const float4* wr = (const float4*)(w + (size_t)co * 768);
        float acc[8] = {};
#pragma unroll 2
        for (int j4 = 0; j4 < 192; j4++) {
            float4 w4 = wr[j4];
#pragma unroll
            for (int i = 0; i < 8; i++) {
                float4 s4 = *(const float4*)&sp[i][j4 * 4];
                acc[i] = fmaf(s4.x, w4.x, fmaf(s4.y, w4.y, fmaf(s4.z, w4.z, fmaf(s4.w, w4.w, acc[i]))));
            }
        }
        float bco = bias[co];
#pragma unroll
        for (int i = 0; i < 8; i++) sx[i][co] = acc[i] + bco;
    }
    __syncthreads();
    {
        const float4* w0 = (const float4*)(qkw + (size_t)co * DIM);
        const float4* w1 = (const float4*)(qkw + (size_t)(DIM + co) * DIM);
        float acc0[8] = {}, acc1[8] = {};
#pragma unroll 2
        for (int j4 = 0; j4 < 64; j4++) {
            float4 a = w0[j4];
            float4 bq = w1[j4];
#pragma unroll
            for (int i = 0; i < 8; i++) {
                float4 s4 = *(const float4*)&sx[i][j4 * 4];
                acc0[i] = fmaf(s4.x, a.x,  fmaf(s4.y, a.y,  fmaf(s4.z, a.z,  fmaf(s4.w, a.w,  acc0[i]))));
                acc1[i] = fmaf(s4.x, bq.x, fmaf(s4.y, bq.y, fmaf(s4.z, bq.z, fmaf(s4.w, bq.w, acc1[i]))));
            }
        }
        const int h = co >> 5, d = co & 31;
#pragma unroll
        for (int i = 0; i < 8; i++) {
            int bn = bn0 + i;
            int b = bn / NTOK, n = bn % NTOK;
            size_t off = (((size_t)b * HEADS + h) * NTOK + n) * HD + d;
            g_q[off] = acc0[i];
            g_k[off] = acc1[i];
        }
    }
}

// ---------------- 2) scores + softmax -> attn (fp16, pad zeroed) -------------
__global__ __launch_bounds__(256) void softmax_v2() {
    const int bh = blockIdx.x;
    __shared__ float sk[NTOK][33];
    const float* kb = g_k + (size_t)bh * NTOK * HD;
    for (int i = threadIdx.x; i < NTOK * HD; i += 256)
        sk[i >> 5][i & 31] = kb[i];
    __syncthreads();
    const int wid = threadIdx.x >> 5, lane = threadIdx.x & 31;
    for (int n = wid; n < NTOK; n += 8) {
        float qd = g_q[((size_t)bh * NTOK + n) * HD + lane];
        float acc[7] = {};
#pragma unroll
        for (int d = 0; d < HD; d++) {
            float qv = __shfl_sync(0xffffffffu, qd, d);
#pragma unroll
            for (int j = 0; j < 7; j++) {
                int m = j * 32 + lane;
                int mc = m < NTOK ? m : NTOK - 1;
                acc[j] = fmaf(qv, sk[mc][d], acc[j]);
            }
        }
        float sc[7], mx = -INFINITY;
#pragma unroll
        for (int j = 0; j < 7; j++) {
            int m = j * 32 + lane;
            sc[j] = (m < NTOK) ? acc[j] * 0.17677669529663687f : -INFINITY;
            mx = fmaxf(mx, sc[j]);
        }
#pragma unroll
        for (int off = 16; off > 0; off >>= 1)
            mx = fmaxf(mx, __shfl_xor_sync(0xffffffffu, mx, off));
        float sum = 0.f;
#pragma unroll
        for (int j = 0; j < 7; j++) {
            sc[j] = expf(sc[j] - mx);
            sum += sc[j];
        }
#pragma unroll
        for (int off = 16; off > 0; off >>= 1)
            sum += __shfl_xor_sync(0xffffffffu, sum, off);
        float inv = 1.f / sum;
        __half* arow = g_attn + ((size_t)bh * NTOK + n) * AK;
#pragma unroll
        for (int j = 0; j < 7; j++) {
            int m = j * 32 + lane;
            if (m < NTOK)      arow[m] = __float2half(sc[j] * inv);
            else if (m < AK)   arow[m] = __float2half(0.f);
        }
    }
}

// ---------------- 3a) im2col: x -> g_ic[b][32][pix] (fp16) -------------------
__global__ __launch_bounds__(224) void im2col_kernel(const float* __restrict__ x) {
    const int y = blockIdx.x;      // 224
    const int krow = blockIdx.y;   // 32
    const int b = blockIdx.z;      // 4
    const int xx = threadIdx.x;    // 224
    float v = 0.f;
    if (krow < 27) {
        int ci = krow / 9;
        int rr = (krow / 3) % 3;
        int dxx = krow % 3;
        int yy = y + rr - 1, xc = xx + dxx - 1;
        if (yy >= 0 && yy < HW && xc >= 0 && xc < HW)
            v = x[(((size_t)b * CIN + ci) * HW + yy) * HW + xc];
    }
    g_ic[((size_t)b * 32 + krow) * PIX + y * HW + xx] = __float2half(v);
}

// == fp16 GEMM machinery: m16n8k16, 128x128 tile, 256 thr, ldmatrix ==========
// A smem: [128 m][20 words]  (16 data words = 32 halves k, 4 pad)
// B smem: [32 k][68 words]   (64 data words = 128 halves n, 4 pad)
#define STAGES  4
#define A_ST_W  2560        // 128*20
#define B_ST_W  2176        // 32*68
#define GEMM_SMEM (STAGES * (A_ST_W + B_ST_W) * 4)   // 75776 B

// one 16-k block of MMAs (kb_ in {0,16}); 8 warps: wm = w&1, wn = w>>1
#define GEMM_KBLOCK(a_st_, b_st_, kb_)                                        \
    do {                                                                      \
        uint32_t af[4][4], bf[4][2];                                          \
        _Pragma("unroll")                                                     \
        for (int mi = 0; mi < 4; mi++) {                                      \
            uint32_t ad = (a_st_) + (((wm * 64 + mi * 16) * 20 + ((kb_) >> 1) + a_lane) << 2); \
            ldsm_x4(af[mi][0], af[mi][1], af[mi][2], af[mi][3], ad);          \
        }                                                                     \
        {                                                                     \
            uint32_t bd0 = (b_st_) + (((kb_) * 68 + b_lane + wn * 16) << 2);  \
            ldsm_x4_t(bf[0][0], bf[0][1], bf[1][0], bf[1][1], bd0);           \
            ldsm_x4_t(bf[2][0], bf[2][1], bf[3][0], bf[3][1], bd0 + 32);      \
        }                                                                     \
        _Pragma("unroll")                                                     \
        for (int mi = 0; mi < 4; mi++)                                        \
            _Pragma("unroll")                                                 \
            for (int ni = 0; ni < 4; ni++)                                    \
                mma_f16(acc[mi][ni], af[mi][0], af[mi][1], af[mi][2],         \
                        af[mi][3], bf[ni][0], bf[ni][1]);                     \
    } while (0)

// ---------------- 3b) conv GEMM: g_cw @ g_ic -> g_vu (fused unfold + bias) ---
// per batch: C[256ch, PIX] , K=32 single tile
__global__ __launch_bounds__(256) void gemm_conv_f16(const float* __restrict__ vb) {
    __shared__ __align__(16) uint32_t sA[A_ST_W];
    __shared__ __align__(16) uint32_t sB[B_ST_W];
    const uint32_t a_st = smem_u32(sA);
    const uint32_t b_st = smem_u32(sB);

    const int b = blockIdx.z;
    const int row0 = blockIdx.y * 128;   // channel block
    const int col0 = blockIdx.x * 128;   // pixel block
    const int t = threadIdx.x;
    const int lane = t & 31, w = t >> 5;
    const int wm = w & 1, wn = w >> 1;
    const int fg = lane >> 2, ftg = lane & 3;
    const int a_lane = ((lane & 7) + ((lane >> 3) & 1) * 8) * 20 + ((lane >> 4) & 1) * 4;
    const int b_lane = ((lane & 7) + ((lane >> 3) & 1) * 8) * 68 + ((lane >> 4) & 1) * 4;
    float acc[4][4][4] = {};

    {   // single-shot loads
        int arow = t >> 1, aq = (t & 1) * 2;
        uint32_t ad = a_st + (arow * 20 + aq * 4) * 4;
        const char* asrc = (const char*)g_cw + (row0 + arow) * 64 + aq * 16;
        cp16(ad,      asrc,      true);
        cp16(ad + 16, asrc + 16, true);
        int bkr = t >> 4, bnc = t & 15;
        uint32_t bd = b_st + (bkr * 68 + bnc * 4) * 4;
        const __half* bsrc = g_ic + ((size_t)b * 32 + bkr) * PIX + col0 + bnc * 8;
        cp16(bd,               bsrc,            true);
        cp16(bd + 16 * 68 * 4, bsrc + 16 * PIX, true);
    }
    CP_COMMIT();
    CP_WAIT0();
    __syncthreads();

    GEMM_KBLOCK(a_st, b_st, 0);
    GEMM_KBLOCK(a_st, b_st, 16);

    // epilogue: bias + scatter into unfolded g_vu layout
#pragma unroll
    for (int mi = 0; mi < 4; mi++) {
#pragma unroll
        for (int half = 0; half < 2; half++) {
            int co = row0 + wm * 64 + mi * 16 + fg + half * 8;
            float bias = vb[co];
            int h = co >> 5, cr = co & 31;
            const int bh = b * HEADS + h;
#pragma unroll
            for (int ni = 0; ni < 4; ni++) {
                int pix = col0 + wn * 32 + ni * 8 + ftg * 2;
                int yy = pix / HW, xx = pix - (pix / HW) * HW;   // xx even -> pair intra-patch
                int n = (yy >> 4) * HP + (xx >> 4);
                int dp = cr * 256 + (yy & 15) * PATCH + (xx & 15);
                __half2 v = __floats2half2_rn(acc[mi][ni][half * 2 + 0] + bias,
                                              acc[mi][ni][half * 2 + 1] + bias);
                *(__half2*)&g_vu[((size_t)bh * NTOK + n) * DP + dp] = v;
            }
        }
    }
}

// ---------------- 4) attn @ vu -> pre (exact R12) -----------------------------
__global__ __launch_bounds__(256, 2) void gemm_attn_vu_f16() {
    extern __shared__ __align__(16) uint32_t dynw[];
    const uint32_t a_u32 = smem_u32(dynw);
    const uint32_t b_u32 = a_u32 + STAGES * A_ST_W * 4;

    const int bh = blockIdx.z;
    const int b = bh >> 3, h = bh & 7;
    const __half* __restrict__ Ah = g_attn + (size_t)bh * NTOK * AK;
    const __half* __restrict__ Bh = g_vu + (size_t)bh * NTOK * DP;
    const int row0 = blockIdx.y * 128;
    const int col0 = blockIdx.x * 128;
    const int t = threadIdx.x;
    const int lane = t & 31, w = t >> 5;
    const int wm = w & 1, wn = w >> 1;
    const int fg = lane >> 2, ftg = lane & 3;
    const int a_lane = ((lane & 7) + ((lane >> 3) & 1) * 8) * 20 + ((lane >> 4) & 1) * 4;
    const int b_lane = ((lane & 7) + ((lane >> 3) & 1) * 8) * 68 + ((lane >> 4) & 1) * 4;
    const int arow = t >> 1, aq = (t & 1) * 2;
    const int bkr = t >> 4, bnc = t & 15;
    float acc[4][4][4] = {};

#define AVU_ISSUE(st_, kt_)                                                   \
    do {                                                                      \
        int gm = row0 + arow;                                                 \
        uint32_t ad = a_u32 + ((st_) * A_ST_W + arow * 20 + aq * 4) * 4;      \
        const char* asrc = (const char*)Ah + gm * (AK * 2) + (kt_) * 64 + aq * 16; \
        bool pm = (gm < NTOK);                                                \
        cp16(ad,      asrc,      pm && ((kt_) * 64 + aq * 16)      < AK * 2); \
        cp16(ad + 16, asrc + 16, pm && ((kt_) * 64 + aq * 16 + 16) < AK * 2); \
        int gk0 = (kt_) * 32 + bkr;                                           \
        int gk1 = gk0 + 16;                                                   \
        uint32_t bd = b_u32 + ((st_) * B_ST_W + bkr * 68 + bnc * 4) * 4;      \
        cp16(bd, Bh + (size_t)gk0 * DP + col0 + bnc * 8, gk0 < NTOK);         \
        cp16(bd + 16 * 68 * 4, Bh + (size_t)gk1 * DP + col0 + bnc * 8, gk1 < NTOK); \
    } while (0)

    const int NK = 7;   // ceil(196/32)
#pragma unroll
    for (int p = 0; p < STAGES - 1; p++) { AVU_ISSUE(p, p); CP_COMMIT(); }
    CP_WAIT2();
    __syncthreads();
#pragma unroll 1
    for (int it = 0; it < NK; it++) {
        int pf = it + STAGES - 1;
        if (pf < NK) AVU_ISSUE(pf & 3, pf);
        CP_COMMIT();
        uint32_t a_st = a_u32 + (it & 3) * A_ST_W * 4;
        uint32_t b_st = b_u32 + (it & 3) * B_ST_W * 4;
        GEMM_KBLOCK(a_st, b_st, 0);
        GEMM_KBLOCK(a_st, b_st, 16);
        CP_WAIT2();
        __syncthreads();
    }
#undef AVU_ISSUE

    // epilogue: fold-scatter into fp16 NCHW pre (__half2 per dp-pair)
#pragma unroll
    for (int mi = 0; mi < 4; mi++) {
#pragma unroll
        for (int half = 0; half < 2; half++) {
            int m = row0 + wm * 64 + mi * 16 + fg + half * 8;
            if (m >= NTOK) continue;
            int hp = m / HP, wp = m % HP;
#pragma unroll
            for (int ni = 0; ni < 4; ni++) {
                int dp = col0 + wn * 32 + ni * 8 + ftg * 2;
                int cr = dp >> 8, rem = dp & 255;
                int pi = rem >> 4, pj = rem & 15;
                int c = h * 32 + cr;
                int pix = (hp * PATCH + pi) * HW + wp * PATCH + pj;
                __half2 v = __floats2half2_rn(acc[mi][ni][half * 2 + 0],
                                              acc[mi][ni][half * 2 + 1]);
                *(__half2*)&g_pre[((size_t)b * DIM + c) * PIX + pix] = v;
            }
        }
    }
}

// ---------------- 5) 1x1 proj (exact R12) --------------------------------------
__global__ __launch_bounds__(256, 2) void gemm_proj_f16(
        const float* __restrict__ pb,
        float* __restrict__ out) {
    extern __shared__ __align__(16) uint32_t dynw[];
    const uint32_t a_u32 = smem_u32(dynw);
    const uint32_t b_u32 = a_u32 + STAGES * A_ST_W * 4;

    const int b = blockIdx.z;
    const __half* __restrict__ Bh = g_pre + (size_t)b * DIM * PIX;
    float* __restrict__ C = out + (size_t)b * DIM * PIX;
    const int row0 = blockIdx.y * 128;
    const int col0 = blockIdx.x * 128;
    const int t = threadIdx.x;
    const int lane = t & 31, w = t >> 5;
    const int wm = w & 1, wn = w >> 1;
    const int fg = lane >> 2, ftg = lane & 3;
    const int a_lane = ((lane & 7) + ((lane >> 3) & 1) * 8) * 20 + ((lane >> 4) & 1) * 4;
    const int b_lane = ((lane & 7) + ((lane >> 3) & 1) * 8) * 68 + ((lane >> 4) & 1) * 4;
    const int arow = t >> 1, aq = (t & 1) * 2;
    const int bkr = t >> 4, bnc = t & 15;
    float acc[4][4][4] = {};

#define PROJ_ISSUE(st_, kt_)                                                  \
    do {                                                                      \
        uint32_t ad = a_u32 + ((st_) * A_ST_W + arow * 20 + aq * 4) * 4;      \
        const char* asrc = (const char*)g_pw + (row0 + arow) * (DIM * 2) + (kt_) * 64 + aq * 16; \
        cp16(ad,      asrc,      true);                                       \
        cp16(ad + 16, asrc + 16, true);                                       \
        int gk0 = (kt_) * 32 + bkr;                                           \
        uint32_t bd = b_u32 + ((st_) * B_ST_W + bkr * 68 + bnc * 4) * 4;      \
        cp16(bd, Bh + (size_t)gk0 * PIX + col0 + bnc * 8, true);              \
        cp16(bd + 16 * 68 * 4, Bh + (size_t)(gk0 + 16) * PIX + col0 + bnc * 8, true); \
    } while (0)

    const int NK = 8;   // 256/32
#pragma unroll
    for (int p = 0; p < STAGES - 1; p++) { PROJ_ISSUE(p, p); CP_COMMIT(); }
    CP_WAIT2();
    __syncthreads();
#pragma unroll 1
    for (int it = 0; it < NK; it++) {
        int pf = it + STAGES - 1;
        if (pf < NK) PROJ_ISSUE(pf & 3, pf);
        CP_COMMIT();
        uint32_t a_st = a_u32 + (it & 3) * A_ST_W * 4;
        uint32_t b_st = b_u32 + (it & 3) * B_ST_W * 4;
        GEMM_KBLOCK(a_st, b_st, 0);
        GEMM_KBLOCK(a_st, b_st, 16);
        CP_WAIT2();
        __syncthreads();
    }
#undef PROJ_ISSUE

#pragma unroll
    for (int mi = 0; mi < 4; mi++) {
#pragma unroll
        for (int half = 0; half < 2; half++) {
            int co = row0 + wm * 64 + mi * 16 + fg + half * 8;
            float bias = pb[co];
            float* crow = &C[(size_t)co * PIX + col0 + wn * 32 + ftg * 2];
#pragma unroll
            for (int ni = 0; ni < 4; ni++) {
                float2 v = make_float2(acc[mi][ni][half * 2 + 0] + bias,
                                       acc[mi][ni][half * 2 + 1] + bias);
                *(float2*)&crow[ni * 8] = v;
            }
        }
    }
}

// ---------------- launch -----------------------------------------------------
extern "C" void kernel_launch(void* const* d_in, const int* in_sizes, int n_in,
                              void* d_out, int out_size) {
    const float* x       = (const float*)d_in[0];
    const float* patch_w = (const float*)d_in[1];
    const float* patch_b = (const float*)d_in[2];
    const float* qk_w    = (const float*)d_in[3];
    const float* v_w     = (const float*)d_in[4];
    const float* v_b     = (const float*)d_in[5];
    const float* proj_w  = (const float*)d_in[6];
    const float* proj_b  = (const float*)d_in[7];
    float* out = (float*)d_out;

    cudaFuncSetAttribute(gemm_attn_vu_f16,
                         cudaFuncAttributeMaxDynamicSharedMemorySize, GEMM_SMEM);
    cudaFuncSetAttribute(gemm_proj_f16,
                         cudaFuncAttributeMaxDynamicSharedMemorySize, GEMM_SMEM);

    patchqk16<<<BATCH * NTOK / 8, 256>>>(x, patch_w, patch_b, qk_w);
    softmax_v2<<<BATCH * HEADS, 256>>>();
    im2col_kernel<<<dim3(HW, 32, BATCH), 224>>>(x);
    cvt_vw_kernel<<<1, 256>>>(v_w);
    gemm_conv_f16<<<dim3(PIX / 128, 2, BATCH), 256>>>(v_b);
    gemm_attn_vu_f16<<<dim3(DP / 128, 2, BATCH * HEADS), 256, GEMM_SMEM>>>();
    cvt_pw_kernel<<<DIM * DIM / 256, 256>>>(proj_w);
    gemm_proj_f16<<<dim3(PIX / 128, 2, BATCH), 256, GEMM_SMEM>>>(proj_b, out);
}